// round 3
// baseline (speedup 1.0000x reference)
#include <cuda_runtime.h>
#include <cuda_bf16.h>
#include <math.h>

// Problem constants
#define Hh 16
#define HS 64
#define E  1024
#define Tt 2048
#define Bb 4
#define PF 4
#define BT (Bb*Tt)          // 8192
#define E3 (3*E)            // 3072
#define FE (PF*E)           // 4096

// ---------------- scratch (device globals; no allocation allowed) -----------
__device__ float g_h   [BT * E];      // LN output / attn-out / LN2 output (reused)
__device__ float g_qkv [BT * E3];     // packed q,k,v rows
__device__ float g_x1  [BT * E];      // x + attn proj (residual stream)
__device__ float g_ff1 [BT * FE];     // relu(h2@W1+b1)
__device__ float g_wqkv[E * E3];      // packed weights [e][{q,k,v}*1024 + h*64 + d]

// ---------------- LayerNorm (torch unbiased var, eps inside sqrt) -----------
__device__ __forceinline__ float block_sum_256(float v, float* red) {
    #pragma unroll
    for (int o = 16; o > 0; o >>= 1) v += __shfl_xor_sync(0xffffffffu, v, o);
    int lane = threadIdx.x & 31, w = threadIdx.x >> 5;
    if (lane == 0) red[w] = v;
    __syncthreads();
    float r = (threadIdx.x < 8) ? red[threadIdx.x] : 0.f;
    if (w == 0) {
        #pragma unroll
        for (int o = 4; o > 0; o >>= 1) r += __shfl_xor_sync(0xffu, r, o);
        if (lane == 0) red[0] = r;
    }
    __syncthreads();
    float out = red[0];
    __syncthreads();
    return out;
}

__global__ void ln_kernel(const float* __restrict__ x, const float* __restrict__ gain,
                          const float* __restrict__ bias, float* __restrict__ o) {
    __shared__ float red[8];
    long row = blockIdx.x;
    const float4* xr = (const float4*)(x + row * E);
    int tid = threadIdx.x;                   // 256 threads, 4 elems each
    float4 v = xr[tid];
    float s = v.x + v.y + v.z + v.w;
    float mean = block_sum_256(s, red) * (1.0f / E);
    float dx = v.x - mean, dy = v.y - mean, dz = v.z - mean, dw = v.w - mean;
    float sq = dx*dx + dy*dy + dz*dz + dw*dw;
    float var = block_sum_256(sq, red) * (1.0f / (E - 1));
    float inv = 1.0f / sqrtf(var + 1e-5f);
    float4 g = ((const float4*)gain)[tid];
    float4 b = ((const float4*)bias)[tid];
    float4 r;
    r.x = dx * inv * g.x + b.x;
    r.y = dy * inv * g.y + b.y;
    r.z = dz * inv * g.z + b.z;
    r.w = dw * inv * g.w + b.w;
    ((float4*)(o + row * E))[tid] = r;
}

// ---------------- pack Wq/Wk/Wv [H,E,HS] -> [E, 3*H*HS] ---------------------
__global__ void pack_wqkv(const float* __restrict__ Wq, const float* __restrict__ Wk,
                          const float* __restrict__ Wv, float* __restrict__ out) {
    int idx = blockIdx.x * 256 + threadIdx.x;
    if (idx >= E * E3) return;
    int n = idx % E3, e = idx / E3;
    int s = n >> 10, r = n & 1023, h = r >> 6, d = r & 63;
    const float* W = (s == 0) ? Wq : (s == 1) ? Wk : Wv;
    out[idx] = W[h * (E * HS) + e * HS + d];
}

// ================= TF32 tensor-core GEMM (mma.sync m16n8k8) =================
// Block tile 128x128, K-stage 16, double-buffered, fragment-permuted smem.
// 8 warps: warp_m = wid&1 (64 rows), warp_n = wid>>1 (32 cols).
// MODE 0: C = A@B ; MODE 1: C = A@B + bias + res ; MODE 2: C = relu(A@B + bias)

__device__ __forceinline__ unsigned f2tf32(float x) {
    unsigned u;
    asm("cvt.rna.tf32.f32 %0, %1;" : "=r"(u) : "f"(x));
    return u;
}

// scatter one A float4 (tile row ar, cols ac4*4..+3) into permuted layout
__device__ __forceinline__ void stageA(unsigned* As, int f, float4 v) {
    int ar = f >> 2, ac4 = f & 3;
    int rr = ar & 15, mt = ar >> 4;
    float vals[4] = {v.x, v.y, v.z, v.w};
    #pragma unroll
    for (int e = 0; e < 4; e++) {
        int c = ac4 * 4 + e;
        int ks = c >> 3;
        int slot = ((rr >> 3) & 1) + (((c & 7) >= 4) ? 2 : 0);
        int ln = (rr & 7) * 4 + (c & 3);
        As[((((mt << 1) + ks) << 5) + ln) * 4 + slot] = f2tf32(vals[e]);
    }
}

// scatter one B float4 (tile k-row kr, cols nc4*4..+3)
__device__ __forceinline__ void stageB(unsigned* Bs, int f, float4 v) {
    int kr = f >> 5, nc4 = f & 31;
    int ks = kr >> 3, krr = kr & 7;
    int slot = krr >> 2;
    float vals[4] = {v.x, v.y, v.z, v.w};
    #pragma unroll
    for (int e = 0; e < 4; e++) {
        int n = nc4 * 4 + e;
        int ln = (n & 7) * 4 + (krr & 3);
        int nt = n >> 3;
        Bs[((((nt << 1) + ks) << 5) + ln) * 2 + slot] = f2tf32(vals[e]);
    }
}

#define MMA_TF32(c, a, b)                                                         \
    asm volatile("mma.sync.aligned.m16n8k8.row.col.f32.tf32.tf32.f32 "            \
                 "{%0,%1,%2,%3},{%4,%5,%6,%7},{%8,%9},{%0,%1,%2,%3};"             \
                 : "+f"(c[0]), "+f"(c[1]), "+f"(c[2]), "+f"(c[3])                  \
                 : "r"(a.x), "r"(a.y), "r"(a.z), "r"(a.w), "r"(b.x), "r"(b.y))

template<int MODE>
__global__ __launch_bounds__(256, 2) void tgemm128(
    const float* __restrict__ A, const float* __restrict__ B,
    const float* __restrict__ bias, const float* __restrict__ res,
    float* __restrict__ C, int M, int N, int K)
{
    // two buffers, each: A 2048 tf32 + B 2048 tf32
    __shared__ unsigned As[2][2048];
    __shared__ unsigned Bs[2][2048];

    int tid = threadIdx.x;
    int ln = tid & 31, wid = tid >> 5;
    int warp_m = wid & 1, warp_n = wid >> 1;
    int bx = blockIdx.x, by = blockIdx.y;

    const float* Aptr = A + (long)(by * 128) * K;
    const float* Bptr = B + bx * 128;

    // staging: each thread owns float4 indices f0,f1 for both A and B tiles
    int f0 = tid * 2, f1 = tid * 2 + 1;
    int a_r0 = f0 >> 2, a_c0 = (f0 & 3) * 4;
    int a_r1 = f1 >> 2, a_c1 = (f1 & 3) * 4;
    int b_k0 = f0 >> 5, b_n0 = (f0 & 31) * 4;
    int b_k1 = f1 >> 5, b_n1 = (f1 & 31) * 4;

    float acc[4][4][4];
    #pragma unroll
    for (int i = 0; i < 4; i++)
        #pragma unroll
        for (int j = 0; j < 4; j++)
            #pragma unroll
            for (int e = 0; e < 4; e++) acc[i][j][e] = 0.f;

    // prologue: stage tile 0
    {
        float4 av0 = *(const float4*)(Aptr + (long)a_r0 * K + a_c0);
        float4 av1 = *(const float4*)(Aptr + (long)a_r1 * K + a_c1);
        float4 bv0 = *(const float4*)(Bptr + (long)b_k0 * N + b_n0);
        float4 bv1 = *(const float4*)(Bptr + (long)b_k1 * N + b_n1);
        stageA(As[0], f0, av0); stageA(As[0], f1, av1);
        stageB(Bs[0], f0, bv0); stageB(Bs[0], f1, bv1);
    }
    __syncthreads();

    int niter = K >> 4;
    for (int it = 0; it < niter; it++) {
        const unsigned* Asb = As[it & 1];
        const unsigned* Bsb = Bs[it & 1];

        float4 av0, av1, bv0, bv1;
        bool has_next = (it + 1) < niter;
        if (has_next) {
            int k0 = (it + 1) << 4;
            av0 = *(const float4*)(Aptr + (long)a_r0 * K + k0 + a_c0);
            av1 = *(const float4*)(Aptr + (long)a_r1 * K + k0 + a_c1);
            bv0 = *(const float4*)(Bptr + (long)(k0 + b_k0) * N + b_n0);
            bv1 = *(const float4*)(Bptr + (long)(k0 + b_k1) * N + b_n1);
        }

        #pragma unroll
        for (int ks = 0; ks < 2; ks++) {
            uint4 af[4];
            uint2 bf[4];
            #pragma unroll
            for (int mt = 0; mt < 4; mt++)
                af[mt] = ((const uint4*)Asb)[(((warp_m * 4 + mt) << 1) + ks) * 32 + ln];
            #pragma unroll
            for (int nt = 0; nt < 4; nt++)
                bf[nt] = ((const uint2*)Bsb)[(((warp_n * 4 + nt) << 1) + ks) * 32 + ln];
            #pragma unroll
            for (int mt = 0; mt < 4; mt++)
                #pragma unroll
                for (int nt = 0; nt < 4; nt++)
                    MMA_TF32(acc[mt][nt], af[mt], bf[nt]);
        }

        if (has_next) {
            unsigned* Asn = As[(it + 1) & 1];
            unsigned* Bsn = Bs[(it + 1) & 1];
            stageA(Asn, f0, av0); stageA(Asn, f1, av1);
            stageB(Bsn, f0, bv0); stageB(Bsn, f1, bv1);
        }
        __syncthreads();
    }

    // epilogue
    int row_base = by * 128 + warp_m * 64;
    int col_base = bx * 128 + warp_n * 32;
    int g = ln >> 2, tg = ln & 3;
    #pragma unroll
    for (int mt = 0; mt < 4; mt++) {
        #pragma unroll
        for (int nt = 0; nt < 4; nt++) {
            int r0 = row_base + mt * 16 + g;
            int c0 = col_base + nt * 8 + tg * 2;
            float2 v0 = make_float2(acc[mt][nt][0], acc[mt][nt][1]);
            float2 v1 = make_float2(acc[mt][nt][2], acc[mt][nt][3]);
            if (MODE == 1 || MODE == 2) {
                float2 bvec = *(const float2*)(bias + c0);
                v0.x += bvec.x; v0.y += bvec.y;
                v1.x += bvec.x; v1.y += bvec.y;
            }
            long off0 = (long)r0 * N + c0;
            long off1 = (long)(r0 + 8) * N + c0;
            if (MODE == 1) {
                float2 r0v = *(const float2*)(res + off0);
                float2 r1v = *(const float2*)(res + off1);
                v0.x += r0v.x; v0.y += r0v.y;
                v1.x += r1v.x; v1.y += r1v.y;
            }
            if (MODE == 2) {
                v0.x = fmaxf(v0.x, 0.f); v0.y = fmaxf(v0.y, 0.f);
                v1.x = fmaxf(v1.x, 0.f); v1.y = fmaxf(v1.y, 0.f);
            }
            *(float2*)(C + off0) = v0;
            *(float2*)(C + off1) = v1;
        }
    }
}

// ---------------- causal flash attention (fp32) ------------------------------
__global__ __launch_bounds__(64) void attn_kernel(const float* __restrict__ qkv,
                                                  float* __restrict__ out) {
    __shared__ float Ksh[64 * 64];
    __shared__ float Vsh[64 * 64];
    int tidx = threadIdx.x;
    int qtile = blockIdx.x;
    int bh = blockIdx.y;
    int b = bh >> 4, h = bh & 15;
    int t = qtile * 64 + tidx;

    const float* base = qkv + (long)b * Tt * E3 + h * HS;
    const float4* qrow = (const float4*)(base + (long)t * E3);
    float4 q[16];
    #pragma unroll
    for (int i = 0; i < 16; i++) q[i] = qrow[i];

    float acc[64];
    #pragma unroll
    for (int d = 0; d < 64; d++) acc[d] = 0.f;
    float m = -INFINITY, l = 0.f;

    for (int j = 0; j <= qtile; j++) {
        const float* kbase = base + (long)(j * 64) * E3 + E;
        const float* vbase = base + (long)(j * 64) * E3 + 2 * E;
        #pragma unroll 4
        for (int i = 0; i < 64; i++) {
            Ksh[i * 64 + tidx] = kbase[(long)i * E3 + tidx];
            Vsh[i * 64 + tidx] = vbase[(long)i * E3 + tidx];
        }
        __syncthreads();

        int kmax = t - j * 64 + 1;
        #pragma unroll 1
        for (int kk = 0; kk < 64; kk++) {
            if (kk < kmax) {
                const float4* kr = (const float4*)&Ksh[kk * 64];
                float s = 0.f;
                #pragma unroll
                for (int i = 0; i < 16; i++) {
                    float4 kv = kr[i];
                    s = fmaf(q[i].x, kv.x, s);
                    s = fmaf(q[i].y, kv.y, s);
                    s = fmaf(q[i].z, kv.z, s);
                    s = fmaf(q[i].w, kv.w, s);
                }
                s *= 8.0f;
                const float* vr = &Vsh[kk * 64];
                if (s > m) {
                    float corr = __expf(m - s);
                    m = s;
                    l = l * corr + 1.0f;
                    #pragma unroll
                    for (int d = 0; d < 64; d++)
                        acc[d] = fmaf(acc[d], corr, vr[d]);
                } else {
                    float p = __expf(s - m);
                    l += p;
                    #pragma unroll
                    for (int d = 0; d < 64; d++)
                        acc[d] = fmaf(p, vr[d], acc[d]);
                }
            }
        }
        __syncthreads();
    }

    float inv = 1.0f / l;
    float* orow = out + ((long)b * Tt + t) * E + h * HS;
    #pragma unroll
    for (int d = 0; d < 64; d++) orow[d] = acc[d] * inv;
}

// ---------------- launch ------------------------------------------------------
extern "C" void kernel_launch(void* const* d_in, const int* in_sizes, int n_in,
                              void* d_out, int out_size) {
    const float* x   = (const float*)d_in[0];
    const float* Wq  = (const float*)d_in[1];
    const float* Wk  = (const float*)d_in[2];
    const float* Wv  = (const float*)d_in[3];
    const float* Wp  = (const float*)d_in[4];
    const float* bp  = (const float*)d_in[5];
    const float* W1  = (const float*)d_in[6];
    const float* b1  = (const float*)d_in[7];
    const float* W2  = (const float*)d_in[8];
    const float* b2  = (const float*)d_in[9];
    const float* g1  = (const float*)d_in[10];
    const float* be1 = (const float*)d_in[11];
    const float* g2  = (const float*)d_in[12];
    const float* be2 = (const float*)d_in[13];
    float* out = (float*)d_out;

    float *ph, *pqkv, *px1, *pff1, *pwqkv;
    cudaGetSymbolAddress((void**)&ph,    g_h);
    cudaGetSymbolAddress((void**)&pqkv,  g_qkv);
    cudaGetSymbolAddress((void**)&px1,   g_x1);
    cudaGetSymbolAddress((void**)&pff1,  g_ff1);
    cudaGetSymbolAddress((void**)&pwqkv, g_wqkv);

    // 1. pack qkv weights
    pack_wqkv<<<(E * E3 + 255) / 256, 256>>>(Wq, Wk, Wv, pwqkv);

    // 2. h = LN1(x)
    ln_kernel<<<BT, 256>>>(x, g1, be1, ph);

    // 3. qkv = h @ Wqkv   [8192,1024] x [1024,3072]
    tgemm128<0><<<dim3(E3 / 128, BT / 128), 256>>>(ph, pwqkv, nullptr, nullptr,
                                                   pqkv, BT, E3, E);

    // 4. attention -> concat-head output into g_h (reused)
    attn_kernel<<<dim3(Tt / 64, Bb * Hh), 64>>>(pqkv, ph);

    // 5. x1 = x + attn_out @ Wp + bp
    tgemm128<1><<<dim3(E / 128, BT / 128), 256>>>(ph, Wp, bp, x, px1, BT, E, E);

    // 6. h2 = LN2(x1)
    ln_kernel<<<BT, 256>>>(px1, g2, be2, ph);

    // 7. ff1 = relu(h2 @ W1 + b1)
    tgemm128<2><<<dim3(FE / 128, BT / 128), 256>>>(ph, W1, b1, nullptr, pff1, BT, FE, E);

    // 8. out = x1 + ff1 @ W2 + b2
    tgemm128<1><<<dim3(E / 128, BT / 128), 256>>>(pff1, W2, b2, px1, out, BT, E, FE);
}

// round 7
// speedup vs baseline: 2.2158x; 2.2158x over previous
#include <cuda_runtime.h>
#include <cuda_fp16.h>
#include <math.h>
#include <stdint.h>

#define Hh 16
#define HS 64
#define E  1024
#define Tt 2048
#define Bq 4
#define BT (Bq*Tt)          // 8192
#define E3 (3*E)            // 3072
#define FE 4096

// ---------------- scratch (A-perm u32 buffers, B packs, fp32 streams) --------
// A-perm layout: u32[(mbG*KD16 + kc)*128 + lane*4 + i2], KD16 = K/16
__device__ __align__(16) uint32_t g_hA  [(long)(BT/16) * 64  * 128];   // K=1024
__device__ __align__(16) uint32_t g_ff1A[(long)(BT/16) * 256 * 128];   // K=4096
__device__ __align__(16) float    g_qkv [(long)BT * E3];
__device__ __align__(16) float    g_x1  [(long)BT * E];
// B-pack layout: u32[((kc*NBt + nb)*32 + lane)*2 + j]
__device__ __align__(16) uint32_t g_wqkvB[(long)E/16  * (E3/8) * 64];
__device__ __align__(16) uint32_t g_wpB  [(long)E/16  * (E/8)  * 64];
__device__ __align__(16) uint32_t g_w1B  [(long)E/16  * (FE/8) * 64];
__device__ __align__(16) uint32_t g_w2B  [(long)FE/16 * (E/8)  * 64];

// ---------------- helpers ----------------------------------------------------
__device__ __forceinline__ uint32_t h2u(float a, float b) {
    __half2 h = __floats2half2_rn(a, b);
    return *(uint32_t*)&h;
}
__device__ __forceinline__ void cpa16(uint32_t dst, const void* src) {
    asm volatile("cp.async.cg.shared.global [%0], [%1], 16;" :: "r"(dst), "l"(src));
}
#define CP_COMMIT() asm volatile("cp.async.commit_group;" ::: "memory")
#define CP_WAIT2()  asm volatile("cp.async.wait_group 2;" ::: "memory")
__device__ __forceinline__ uint32_t smem_u32(const void* p) {
    uint32_t a;
    asm("{ .reg .u64 t; cvta.to.shared.u64 t, %1; cvt.u32.u64 %0, t; }" : "=r"(a) : "l"(p));
    return a;
}
#define MMA16816(c, a, b)                                                        \
    asm volatile("mma.sync.aligned.m16n8k16.row.col.f32.f16.f16.f32 "            \
                 "{%0,%1,%2,%3},{%4,%5,%6,%7},{%8,%9},{%0,%1,%2,%3};"            \
                 : "+f"(c[0]), "+f"(c[1]), "+f"(c[2]), "+f"(c[3])                 \
                 : "r"(a.x), "r"(a.y), "r"(a.z), "r"(a.w), "r"(b.x), "r"(b.y))

// ================= fp16 tensor GEMM, pre-permuted operands ===================
// C[128,128] tile per CTA, 8 warps (2m x 4n), warp tile 64x32, K-iter = 16.
// MODE 0: fp32 C; MODE 1: fp32 C+bias+res; MODE 2: A-perm half relu(C+bias)
template<int MODE>
__global__ __launch_bounds__(256) void hgemm(
    const uint32_t* __restrict__ Aperm, const uint32_t* __restrict__ Bpk,
    const float* __restrict__ bias, const float* __restrict__ res,
    void* __restrict__ Cout, int KD16, int N, int KD16out)
{
    __shared__ __align__(16) uint8_t smArr[4 * 8192];   // 4 stages x (A 4KB + B 4KB)
    uint32_t sb = smem_u32(smArr);
    const int tid = threadIdx.x;
    const int ln = tid & 31, wid = tid >> 5;
    const int warp_m = wid & 1, warp_n = wid >> 1;
    const int m0 = blockIdx.y * 128, n0 = blockIdx.x * 128;
    const int NBt = N >> 3;
    const int nb0 = n0 >> 3;

    const char* Ag = (const char*)Aperm;
    const char* Bg = (const char*)Bpk;
    const int a_mb = tid >> 5;            // 8 m-blocks
    const int b_nbt = tid >> 4, b_q = tid & 15;   // 16 n-blocks, 16B chunks

    auto load_stage = [&](int c) {
        int s = c & 3;
        cpa16(sb + s * 8192 + a_mb * 512 + ln * 16,
              Ag + (((long)(m0 / 16 + a_mb) * KD16 + c) * 512) + ln * 16);
        cpa16(sb + s * 8192 + 4096 + b_nbt * 256 + b_q * 16,
              Bg + (((long)c * NBt + nb0 + b_nbt) * 256) + b_q * 16);
        CP_COMMIT();
    };

    float acc[4][4][4];
    #pragma unroll
    for (int i = 0; i < 4; i++)
        #pragma unroll
        for (int j = 0; j < 4; j++)
            #pragma unroll
            for (int e = 0; e < 4; e++) acc[i][j][e] = 0.f;

    load_stage(0); load_stage(1); load_stage(2);

    for (int c = 0; c < KD16; c++) {
        CP_WAIT2();
        __syncthreads();
        int pc = c + 3;
        if (pc < KD16) load_stage(pc); else CP_COMMIT();

        uint32_t as = sb + (c & 3) * 8192;
        uint32_t bs = as + 4096;
        uint4 af[4];
        uint2 bf[4];
        #pragma unroll
        for (int mt = 0; mt < 4; mt++)
            asm volatile("ld.shared.v4.u32 {%0,%1,%2,%3}, [%4];"
                : "=r"(af[mt].x), "=r"(af[mt].y), "=r"(af[mt].z), "=r"(af[mt].w)
                : "r"(as + (warp_m * 4 + mt) * 512 + ln * 16));
        #pragma unroll
        for (int nt = 0; nt < 4; nt++)
            asm volatile("ld.shared.v2.u32 {%0,%1}, [%2];"
                : "=r"(bf[nt].x), "=r"(bf[nt].y)
                : "r"(bs + (warp_n * 4 + nt) * 256 + ln * 8));
        #pragma unroll
        for (int mt = 0; mt < 4; mt++)
            #pragma unroll
            for (int nt = 0; nt < 4; nt++)
                MMA16816(acc[mt][nt], af[mt], bf[nt]);
        __syncthreads();
    }

    // epilogue
    const int g = ln >> 2, tg = ln & 3;
    const int row_base = m0 + warp_m * 64;
    const int col_base = n0 + warp_n * 32;
    #pragma unroll
    for (int mt = 0; mt < 4; mt++) {
        #pragma unroll
        for (int nt = 0; nt < 4; nt++) {
            int r0 = row_base + mt * 16 + g;
            int c0 = col_base + nt * 8 + tg * 2;
            float v00 = acc[mt][nt][0], v01 = acc[mt][nt][1];
            float v10 = acc[mt][nt][2], v11 = acc[mt][nt][3];
            if (MODE == 1 || MODE == 2) {
                float b0 = bias[c0], b1 = bias[c0 + 1];
                v00 += b0; v01 += b1; v10 += b0; v11 += b1;
            }
            if (MODE == 0 || MODE == 1) {
                float* C = (float*)Cout;
                long off0 = (long)r0 * N + c0;
                long off1 = (long)(r0 + 8) * N + c0;
                if (MODE == 1) {
                    float2 rv0 = *(const float2*)(res + off0);
                    float2 rv1 = *(const float2*)(res + off1);
                    v00 += rv0.x; v01 += rv0.y; v10 += rv1.x; v11 += rv1.y;
                }
                *(float2*)(C + off0) = make_float2(v00, v01);
                *(float2*)(C + off1) = make_float2(v10, v11);
            } else {
                v00 = fmaxf(v00, 0.f); v01 = fmaxf(v01, 0.f);
                v10 = fmaxf(v10, 0.f); v11 = fmaxf(v11, 0.f);
                uint32_t* Ao = (uint32_t*)Cout;
                int kc = c0 >> 4;
                int i2b = ((c0 & 15) >= 8) ? 2 : 0;
                int lane_p = (g & 7) * 4 + ((c0 & 7) >> 1);
                long base0 = ((long)(r0 >> 4) * KD16out + kc) * 128 + lane_p * 4;
                Ao[base0 + i2b]     = h2u(v00, v01);
                Ao[base0 + i2b + 1] = h2u(v10, v11);
            }
        }
    }
}

// ---------------- LayerNorm -> A-perm ----------------------------------------
__device__ __forceinline__ float block_sum_256(float v, float* red) {
    #pragma unroll
    for (int o = 16; o > 0; o >>= 1) v += __shfl_xor_sync(0xffffffffu, v, o);
    int lane = threadIdx.x & 31, w = threadIdx.x >> 5;
    if (lane == 0) red[w] = v;
    __syncthreads();
    float r = (threadIdx.x < 8) ? red[threadIdx.x] : 0.f;
    if (w == 0) {
        #pragma unroll
        for (int o = 4; o > 0; o >>= 1) r += __shfl_xor_sync(0xffu, r, o);
        if (lane == 0) red[0] = r;
    }
    __syncthreads();
    float out = red[0];
    __syncthreads();
    return out;
}

__global__ void ln_pack(const float* __restrict__ x, const float* __restrict__ gain,
                        const float* __restrict__ bias, uint32_t* __restrict__ o) {
    __shared__ float red[8];
    long row = blockIdx.x;
    int tid = threadIdx.x;
    float4 v = ((const float4*)(x + row * E))[tid];
    float mean = block_sum_256(v.x + v.y + v.z + v.w, red) * (1.0f / E);
    float dx = v.x-mean, dy = v.y-mean, dz = v.z-mean, dw = v.w-mean;
    float var = block_sum_256(dx*dx + dy*dy + dz*dz + dw*dw, red) * (1.0f/(E-1));
    float inv = 1.0f / sqrtf(var + 1e-5f);
    float4 gv = ((const float4*)gain)[tid];
    float4 bv = ((const float4*)bias)[tid];
    float r0 = dx*inv*gv.x + bv.x, r1 = dy*inv*gv.y + bv.y;
    float r2 = dz*inv*gv.z + bv.z, r3 = dw*inv*gv.w + bv.w;
    int r = (int)(row & 15);
    long mbG = row >> 4;
    int kc = tid >> 2, kk0 = (tid & 3) * 4;
    int i2 = (r >= 8 ? 1 : 0) + (kk0 >= 8 ? 2 : 0);
    int lane = (r & 7) * 4 + ((kk0 & 7) >> 1);
    long base = (mbG * 64 + kc) * 128;
    o[base + lane * 4 + i2]       = h2u(r0, r1);
    o[base + (lane + 1) * 4 + i2] = h2u(r2, r3);
}

// ---------------- B pack kernels ----------------------------------------------
__global__ void pack_w(const float* __restrict__ W, int N, long total,
                       uint32_t* __restrict__ out) {
    long idx = (long)blockIdx.x * 256 + threadIdx.x;
    if (idx >= total) return;
    int j = idx & 1;
    int lane = (idx >> 1) & 31;
    long rest = idx >> 6;
    int NBt = N >> 3;
    int nb = (int)(rest % NBt);
    int kc = (int)(rest / NBt);
    int n = nb * 8 + (lane >> 2);
    int k = kc * 16 + j * 8 + (lane & 3) * 2;
    out[idx] = h2u(W[(long)k * N + n], W[(long)(k + 1) * N + n]);
}
__global__ void pack_qkv(const float* __restrict__ Wq, const float* __restrict__ Wk,
                         const float* __restrict__ Wv, uint32_t* __restrict__ out) {
    long idx = (long)blockIdx.x * 256 + threadIdx.x;
    if (idx >= (long)(E/16) * (E3/8) * 64) return;
    int j = idx & 1;
    int lane = (idx >> 1) & 31;
    long rest = idx >> 6;
    int nb = (int)(rest % (E3/8));
    int kc = (int)(rest / (E3/8));
    int n = nb * 8 + (lane >> 2);
    int k = kc * 16 + j * 8 + (lane & 3) * 2;
    int s = n >> 10, rr = n & 1023, h = rr >> 6, d = rr & 63;
    const float* W = (s == 0) ? Wq : (s == 1) ? Wk : Wv;
    long o1 = (long)h * (E * HS) + (long)k * HS + d;
    out[idx] = h2u(W[o1], W[o1 + HS]);
}

// ---------------- causal flash attention (fp32) -> A-perm --------------------
__global__ __launch_bounds__(64) void attn_kernel(const float* __restrict__ qkv,
                                                  uint32_t* __restrict__ out) {
    __shared__ float Ksh[64 * 64];
    __shared__ float Vsh[64 * 64];
    int tidx = threadIdx.x;
    int qtile = blockIdx.x, bh = blockIdx.y;
    int b = bh >> 4, h = bh & 15;
    int t = qtile * 64 + tidx;

    const float* base = qkv + (long)b * Tt * E3 + h * HS;
    const float4* qrow = (const float4*)(base + (long)t * E3);
    float4 q[16];
    #pragma unroll
    for (int i = 0; i < 16; i++) q[i] = qrow[i];

    float acc[64];
    #pragma unroll
    for (int d = 0; d < 64; d++) acc[d] = 0.f;
    float m = -INFINITY, l = 0.f;

    for (int j = 0; j <= qtile; j++) {
        const float* kbase = base + (long)(j*64) * E3 + E;
        const float* vbase = base + (long)(j*64) * E3 + 2*E;
        #pragma unroll 4
        for (int i = 0; i < 64; i++) {
            Ksh[i*64 + tidx] = kbase[(long)i * E3 + tidx];
            Vsh[i*64 + tidx] = vbase[(long)i * E3 + tidx];
        }
        __syncthreads();
        int kmax = t - j*64 + 1;
        #pragma unroll 1
        for (int kk = 0; kk < 64; kk++) {
            if (kk < kmax) {
                const float4* kr = (const float4*)&Ksh[kk*64];
                float s = 0.f;
                #pragma unroll
                for (int i = 0; i < 16; i++) {
                    float4 kv = kr[i];
                    s = fmaf(q[i].x, kv.x, s); s = fmaf(q[i].y, kv.y, s);
                    s = fmaf(q[i].z, kv.z, s); s = fmaf(q[i].w, kv.w, s);
                }
                s *= 8.0f;
                const float* vr = &Vsh[kk*64];
                if (s > m) {
                    float corr = __expf(m - s);
                    m = s; l = l * corr + 1.0f;
                    #pragma unroll
                    for (int d = 0; d < 64; d++) acc[d] = fmaf(acc[d], corr, vr[d]);
                } else {
                    float p = __expf(s - m);
                    l += p;
                    #pragma unroll
                    for (int d = 0; d < 64; d++) acc[d] = fmaf(p, vr[d], acc[d]);
                }
            }
        }
        __syncthreads();
    }
    float inv = 1.0f / l;
    long row = (long)b * Tt + t;
    int r = (int)(row & 15);
    long mbbase = (row >> 4) * 64;
    #pragma unroll
    for (int d = 0; d < 64; d += 2) {
        int k = h * 64 + d;
        int kc = k >> 4;
        int i2 = (r >= 8 ? 1 : 0) + (((k & 15) >= 8) ? 2 : 0);
        int lane = (r & 7) * 4 + ((k & 7) >> 1);
        out[(mbbase + kc) * 128 + lane * 4 + i2] = h2u(acc[d] * inv, acc[d + 1] * inv);
    }
}

// ---------------- launch ------------------------------------------------------
extern "C" void kernel_launch(void* const* d_in, const int* in_sizes, int n_in,
                              void* d_out, int out_size) {
    const float* x   = (const float*)d_in[0];
    const float* Wq  = (const float*)d_in[1];
    const float* Wk  = (const float*)d_in[2];
    const float* Wv  = (const float*)d_in[3];
    const float* Wp  = (const float*)d_in[4];
    const float* bp  = (const float*)d_in[5];
    const float* W1  = (const float*)d_in[6];
    const float* b1  = (const float*)d_in[7];
    const float* W2  = (const float*)d_in[8];
    const float* b2  = (const float*)d_in[9];
    const float* g1  = (const float*)d_in[10];
    const float* be1 = (const float*)d_in[11];
    const float* g2  = (const float*)d_in[12];
    const float* be2 = (const float*)d_in[13];
    float* out = (float*)d_out;

    uint32_t *phA, *pff1A, *pwqkvB, *pwpB, *pw1B, *pw2B;
    float *pqkv, *px1;
    cudaGetSymbolAddress((void**)&phA,    g_hA);
    cudaGetSymbolAddress((void**)&pff1A,  g_ff1A);
    cudaGetSymbolAddress((void**)&pqkv,   g_qkv);
    cudaGetSymbolAddress((void**)&px1,    g_x1);
    cudaGetSymbolAddress((void**)&pwqkvB, g_wqkvB);
    cudaGetSymbolAddress((void**)&pwpB,   g_wpB);
    cudaGetSymbolAddress((void**)&pw1B,   g_w1B);
    cudaGetSymbolAddress((void**)&pw2B,   g_w2B);

    long tq = (long)(E/16) * (E3/8) * 64;
    pack_qkv<<<(int)((tq + 255) / 256), 256>>>(Wq, Wk, Wv, pwqkvB);
    long tp = (long)(E/16) * (E/8) * 64;
    pack_w<<<(int)((tp + 255) / 256), 256>>>(Wp, E, tp, pwpB);
    long t1 = (long)(E/16) * (FE/8) * 64;
    pack_w<<<(int)((t1 + 255) / 256), 256>>>(W1, FE, t1, pw1B);
    long t2 = (long)(FE/16) * (E/8) * 64;
    pack_w<<<(int)((t2 + 255) / 256), 256>>>(W2, E, t2, pw2B);

    ln_pack<<<BT, 256>>>(x, g1, be1, phA);
    hgemm<0><<<dim3(E3/128, BT/128), 256>>>(phA, pwqkvB, nullptr, nullptr, pqkv, 64, E3, 0);
    attn_kernel<<<dim3(Tt/64, Bq*Hh), 64>>>(pqkv, phA);
    hgemm<1><<<dim3(E/128, BT/128), 256>>>(phA, pwpB, bp, x, px1, 64, E, 0);
    ln_pack<<<BT, 256>>>(px1, g2, be2, phA);
    hgemm<2><<<dim3(FE/128, BT/128), 256>>>(phA, pw1B, b1, nullptr, pff1A, 64, FE, 256);
    hgemm<1><<<dim3(E/128, BT/128), 256>>>(pff1A, pw2B, b2, px1, out, 256, E, 0);
}

// round 9
// speedup vs baseline: 3.0358x; 1.3701x over previous
#include <cuda_runtime.h>
#include <cuda_fp16.h>
#include <math.h>
#include <stdint.h>

#define Hh 16
#define HS 64
#define E  1024
#define Tt 2048
#define Bq 4
#define BT (Bq*Tt)          // 8192
#define E3 (3*E)            // 3072
#define FE 4096
#define QSZ 4194304L        // one fragment bank (u32 count)

// ---------------- scratch ------------------------------------------------------
__device__ __align__(16) uint32_t g_hA  [(long)(BT/16) * 64  * 128];   // A-perm K=1024
__device__ __align__(16) uint32_t g_ff1A[(long)(BT/16) * 256 * 128];   // A-perm K=4096
__device__ __align__(16) uint32_t g_frag[6 * QSZ];   // Qhi|Qlo|Khi|Klo|Vhi|Vlo
__device__ __align__(16) float    g_x1  [(long)BT * E];
__device__ __align__(16) uint32_t g_wqkvB[(long)E/16  * (E3/8) * 64];
__device__ __align__(16) uint32_t g_wpB  [(long)E/16  * (E/8)  * 64];
__device__ __align__(16) uint32_t g_w1B  [(long)E/16  * (FE/8) * 64];
__device__ __align__(16) uint32_t g_w2B  [(long)FE/16 * (E/8)  * 64];

// ---------------- helpers ------------------------------------------------------
__device__ __forceinline__ uint32_t h2u(float a, float b) {
    __half2 h = __floats2half2_rn(a, b);
    return *(uint32_t*)&h;
}
__device__ __forceinline__ float flo(float x) {
    return x - __half2float(__float2half_rn(x));
}
// exp in the FMA pipe (no MUFU): exp(x) = 2^(x*log2e), deg-5 poly on [-.5,.5]
__device__ __forceinline__ float fexp(float x) {
    x = fmaxf(x, -87.0f);
    float y  = fmaf(x, 1.44269504f, 12582912.0f);
    float rn = y - 12582912.0f;
    float f  = fmaf(x, 1.44269504f, -rn);
    float p  =            1.33333588e-3f;
    p = fmaf(p, f, 9.61812910e-3f);
    p = fmaf(p, f, 5.55041087e-2f);
    p = fmaf(p, f, 2.40226507e-1f);
    p = fmaf(p, f, 6.93147181e-1f);
    p = fmaf(p, f, 1.0f);
    int n = (int)rn;
    return __int_as_float(__float_as_int(p) + (n << 23));
}
__device__ __forceinline__ void cpa16(uint32_t dst, const void* src) {
    asm volatile("cp.async.cg.shared.global [%0], [%1], 16;" :: "r"(dst), "l"(src));
}
#define CP_COMMIT() asm volatile("cp.async.commit_group;" ::: "memory")
#define CP_WAIT2()  asm volatile("cp.async.wait_group 2;" ::: "memory")
__device__ __forceinline__ uint32_t smem_u32(const void* p) {
    uint32_t a;
    asm("{ .reg .u64 t; cvta.to.shared.u64 t, %1; cvt.u32.u64 %0, t; }" : "=r"(a) : "l"(p));
    return a;
}
#define MMA16816(c, a, b)                                                        \
    asm volatile("mma.sync.aligned.m16n8k16.row.col.f32.f16.f16.f32 "            \
                 "{%0,%1,%2,%3},{%4,%5,%6,%7},{%8,%9},{%0,%1,%2,%3};"            \
                 : "+f"(c[0]), "+f"(c[1]), "+f"(c[2]), "+f"(c[3])                 \
                 : "r"(a.x), "r"(a.y), "r"(a.z), "r"(a.w), "r"(b.x), "r"(b.y))

// ================= fp16 tensor GEMM, pre-permuted operands ======================
// MODE 0: fp32 C; 1: fp32 C+bias+res; 2: A-perm relu(C+bias); 3: QKV hi/lo frags
template<int MODE>
__global__ __launch_bounds__(256) void hgemm(
    const uint32_t* __restrict__ Aperm, const uint32_t* __restrict__ Bpk,
    const float* __restrict__ bias, const float* __restrict__ res,
    void* __restrict__ Cout, int KD16, int N, int KD16out)
{
    __shared__ __align__(16) uint8_t smArr[4 * 8192];
    uint32_t sb = smem_u32(smArr);
    const int tid = threadIdx.x;
    const int ln = tid & 31, wid = tid >> 5;
    const int warp_m = wid & 1, warp_n = wid >> 1;
    const int m0 = blockIdx.y * 128, n0 = blockIdx.x * 128;
    const int NBt = N >> 3;
    const int nb0 = n0 >> 3;

    const char* Ag = (const char*)Aperm;
    const char* Bg = (const char*)Bpk;
    const int a_mb = tid >> 5;
    const int b_nbt = tid >> 4, b_q = tid & 15;

    auto load_stage = [&](int c) {
        int s = c & 3;
        cpa16(sb + s * 8192 + a_mb * 512 + ln * 16,
              Ag + (((long)(m0 / 16 + a_mb) * KD16 + c) * 512) + ln * 16);
        cpa16(sb + s * 8192 + 4096 + b_nbt * 256 + b_q * 16,
              Bg + (((long)c * NBt + nb0 + b_nbt) * 256) + b_q * 16);
        CP_COMMIT();
    };

    float acc[4][4][4];
    #pragma unroll
    for (int i = 0; i < 4; i++)
        #pragma unroll
        for (int j = 0; j < 4; j++)
            #pragma unroll
            for (int e = 0; e < 4; e++) acc[i][j][e] = 0.f;

    load_stage(0); load_stage(1); load_stage(2);

    for (int c = 0; c < KD16; c++) {
        CP_WAIT2();
        __syncthreads();
        int pc = c + 3;
        if (pc < KD16) load_stage(pc); else CP_COMMIT();

        uint32_t as = sb + (c & 3) * 8192;
        uint32_t bs = as + 4096;
        uint4 af[4];
        uint2 bf[4];
        #pragma unroll
        for (int mt = 0; mt < 4; mt++)
            asm volatile("ld.shared.v4.u32 {%0,%1,%2,%3}, [%4];"
                : "=r"(af[mt].x), "=r"(af[mt].y), "=r"(af[mt].z), "=r"(af[mt].w)
                : "r"(as + (warp_m * 4 + mt) * 512 + ln * 16));
        #pragma unroll
        for (int nt = 0; nt < 4; nt++)
            asm volatile("ld.shared.v2.u32 {%0,%1}, [%2];"
                : "=r"(bf[nt].x), "=r"(bf[nt].y)
                : "r"(bs + (warp_n * 4 + nt) * 256 + ln * 8));
        #pragma unroll
        for (int mt = 0; mt < 4; mt++)
            #pragma unroll
            for (int nt = 0; nt < 4; nt++)
                MMA16816(acc[mt][nt], af[mt], bf[nt]);
        __syncthreads();
    }

    const int g = ln >> 2, tg = ln & 3;
    const int row_base = m0 + warp_m * 64;
    const int col_base = n0 + warp_n * 32;
    #pragma unroll
    for (int mt = 0; mt < 4; mt++) {
        #pragma unroll
        for (int nt = 0; nt < 4; nt++) {
            int r0 = row_base + mt * 16 + g;
            int c0 = col_base + nt * 8 + tg * 2;
            float v00 = acc[mt][nt][0], v01 = acc[mt][nt][1];
            float v10 = acc[mt][nt][2], v11 = acc[mt][nt][3];
            if (MODE == 1 || MODE == 2) {
                float b0 = bias[c0], b1 = bias[c0 + 1];
                v00 += b0; v01 += b1; v10 += b0; v11 += b1;
            }
            if (MODE == 0 || MODE == 1) {
                float* C = (float*)Cout;
                long off0 = (long)r0 * N + c0;
                long off1 = (long)(r0 + 8) * N + c0;
                if (MODE == 1) {
                    float2 rv0 = *(const float2*)(res + off0);
                    float2 rv1 = *(const float2*)(res + off1);
                    v00 += rv0.x; v01 += rv0.y; v10 += rv1.x; v11 += rv1.y;
                }
                *(float2*)(C + off0) = make_float2(v00, v01);
                *(float2*)(C + off1) = make_float2(v10, v11);
            } else if (MODE == 2) {
                v00 = fmaxf(v00, 0.f); v01 = fmaxf(v01, 0.f);
                v10 = fmaxf(v10, 0.f); v11 = fmaxf(v11, 0.f);
                uint32_t* Ao = (uint32_t*)Cout;
                int kc = c0 >> 4;
                int i2b = ((c0 & 15) >= 8) ? 2 : 0;
                int lane_p = (g & 7) * 4 + ((c0 & 7) >> 1);
                long base0 = ((long)(r0 >> 4) * KD16out + kc) * 128 + lane_p * 4;
                Ao[base0 + i2b]     = h2u(v00, v01);
                Ao[base0 + i2b + 1] = h2u(v10, v11);
            } else {
                // MODE 3: scatter into Q/K/V hi+lo fragment banks
                uint32_t* F = (uint32_t*)Cout;
                int sct = c0 >> 10;
                int hh  = (c0 >> 6) & 15;
                int d   = c0 & 63;
                int b   = r0 >> 11;
                int t   = r0 & 2047;
                int bh  = b * 16 + hh;
                if (sct == 0) {
                    long off = (((long)(bh * 128 + (t >> 4)) * 4 + (d >> 4)) << 7)
                             + ((t & 7) * 4 + ((d & 7) >> 1)) * 4
                             + (((d & 15) >= 8) ? 2 : 0);
                    F[off]           = h2u(v00, v01);
                    F[off + 1]       = h2u(v10, v11);
                    F[QSZ + off]     = h2u(flo(v00), flo(v01));
                    F[QSZ + off + 1] = h2u(flo(v10), flo(v11));
                } else if (sct == 1) {
                    int ln2 = (t & 7) * 4 + ((d & 7) >> 1);
                    int j = ((d & 15) >= 8) ? 1 : 0;
                    long off = ((long)(bh * 256 + (t >> 3)) * 4 + (d >> 4)) * 64 + ln2 * 2 + j;
                    F[2*QSZ + off]       = h2u(v00, v01);
                    F[2*QSZ + off + 256] = h2u(v10, v11);
                    F[3*QSZ + off]       = h2u(flo(v00), flo(v01));
                    F[3*QSZ + off + 256] = h2u(flo(v10), flo(v11));
                } else {
                    float p00 = __shfl_xor_sync(0xffffffffu, v00, 4);
                    float p01 = __shfl_xor_sync(0xffffffffu, v01, 4);
                    float p10 = __shfl_xor_sync(0xffffffffu, v10, 4);
                    float p11 = __shfl_xor_sync(0xffffffffu, v11, 4);
                    if (!(g & 1)) {
                        int vl2 = (d & 7) * 4 + (g >> 1);
                        long off = ((long)(bh * 128 + (t >> 4)) * 8 + (d >> 3)) * 64 + vl2 * 2;
                        F[4*QSZ + off]     = h2u(v00, p00);
                        F[4*QSZ + off + 1] = h2u(v10, p10);
                        F[4*QSZ + off + 8] = h2u(v01, p01);
                        F[4*QSZ + off + 9] = h2u(v11, p11);
                        F[5*QSZ + off]     = h2u(flo(v00), flo(p00));
                        F[5*QSZ + off + 1] = h2u(flo(v10), flo(p10));
                        F[5*QSZ + off + 8] = h2u(flo(v01), flo(p01));
                        F[5*QSZ + off + 9] = h2u(flo(v11), flo(p11));
                    }
                }
            }
        }
    }
}

// ---------------- LayerNorm -> A-perm -------------------------------------------
__device__ __forceinline__ float block_sum_256(float v, float* red) {
    #pragma unroll
    for (int o = 16; o > 0; o >>= 1) v += __shfl_xor_sync(0xffffffffu, v, o);
    int lane = threadIdx.x & 31, w = threadIdx.x >> 5;
    if (lane == 0) red[w] = v;
    __syncthreads();
    float r = (threadIdx.x < 8) ? red[threadIdx.x] : 0.f;
    if (w == 0) {
        #pragma unroll
        for (int o = 4; o > 0; o >>= 1) r += __shfl_xor_sync(0xffu, r, o);
        if (lane == 0) red[0] = r;
    }
    __syncthreads();
    float out = red[0];
    __syncthreads();
    return out;
}

__global__ void ln_pack(const float* __restrict__ x, const float* __restrict__ gain,
                        const float* __restrict__ bias, uint32_t* __restrict__ o) {
    __shared__ float red[8];
    long row = blockIdx.x;
    int tid = threadIdx.x;
    float4 v = ((const float4*)(x + row * E))[tid];
    float mean = block_sum_256(v.x + v.y + v.z + v.w, red) * (1.0f / E);
    float dx = v.x-mean, dy = v.y-mean, dz = v.z-mean, dw = v.w-mean;
    float var = block_sum_256(dx*dx + dy*dy + dz*dz + dw*dw, red) * (1.0f/(E-1));
    float inv = 1.0f / sqrtf(var + 1e-5f);
    float4 gv = ((const float4*)gain)[tid];
    float4 bv = ((const float4*)bias)[tid];
    float r0 = dx*inv*gv.x + bv.x, r1 = dy*inv*gv.y + bv.y;
    float r2 = dz*inv*gv.z + bv.z, r3 = dw*inv*gv.w + bv.w;
    int r = (int)(row & 15);
    long mbG = row >> 4;
    int kc = tid >> 2, kk0 = (tid & 3) * 4;
    int i2 = (r >= 8 ? 1 : 0) + (kk0 >= 8 ? 2 : 0);
    int lane = (r & 7) * 4 + ((kk0 & 7) >> 1);
    long base = (mbG * 64 + kc) * 128;
    o[base + lane * 4 + i2]       = h2u(r0, r1);
    o[base + (lane + 1) * 4 + i2] = h2u(r2, r3);
}

// ---------------- B pack kernels --------------------------------------------------
__global__ void pack_w(const float* __restrict__ W, int N, long total,
                       uint32_t* __restrict__ out) {
    long idx = (long)blockIdx.x * 256 + threadIdx.x;
    if (idx >= total) return;
    int j = idx & 1;
    int lane = (idx >> 1) & 31;
    long rest = idx >> 6;
    int NBt = N >> 3;
    int nb = (int)(rest % NBt);
    int kc = (int)(rest / NBt);
    int n = nb * 8 + (lane >> 2);
    int k = kc * 16 + j * 8 + (lane & 3) * 2;
    out[idx] = h2u(W[(long)k * N + n], W[(long)(k + 1) * N + n]);
}
__global__ void pack_qkv(const float* __restrict__ Wq, const float* __restrict__ Wk,
                         const float* __restrict__ Wv, uint32_t* __restrict__ out) {
    long idx = (long)blockIdx.x * 256 + threadIdx.x;
    if (idx >= (long)(E/16) * (E3/8) * 64) return;
    int j = idx & 1;
    int lane = (idx >> 1) & 31;
    long rest = idx >> 6;
    int nb = (int)(rest % (E3/8));
    int kc = (int)(rest / (E3/8));
    int n = nb * 8 + (lane >> 2);
    int k = kc * 16 + j * 8 + (lane & 3) * 2;
    int s = n >> 10, rr = n & 1023, h = rr >> 6, d = rr & 63;
    const float* W = (s == 0) ? Wq : (s == 1) ? Wk : Wv;
    long o1 = (long)h * (E * HS) + (long)k * HS + d;
    out[idx] = h2u(W[o1], W[o1 + HS]);
}

// ---------------- MMA flash attention, 3-term hi/lo, FMA-pipe exp -----------------
__global__ __launch_bounds__(128) void attn_mma(const uint32_t* __restrict__ pf,
                                                uint32_t* __restrict__ out) {
    const int qt = 31 - blockIdx.x;
    const int bh = blockIdx.y;
    const int ln = threadIdx.x & 31, wq = threadIdx.x >> 5;
    const int g = ln >> 2, tg = ln & 3;
    const int row0 = qt * 64 + wq * 16 + g;

    uint4 qh[4], qlo[4];
    const uint32_t* qfb = pf + ((long)(bh * 128 + qt * 4 + wq) * 4) * 128 + ln * 4;
    #pragma unroll
    for (int kc = 0; kc < 4; kc++) {
        qh[kc]  = *(const uint4*)(qfb + kc * 128);
        qlo[kc] = *(const uint4*)(qfb + QSZ + kc * 128);
    }

    float oc[8][4];
    #pragma unroll
    for (int i = 0; i < 8; i++) { oc[i][0]=oc[i][1]=oc[i][2]=oc[i][3]=0.f; }
    float m0 = -1e30f, m1 = -1e30f, l0 = 0.f, l1 = 0.f;

    for (int kt = 0; kt <= qt; kt++) {
        float sc[8][4];
        #pragma unroll
        for (int i = 0; i < 8; i++) { sc[i][0]=sc[i][1]=sc[i][2]=sc[i][3]=0.f; }

        const uint32_t* kfb = pf + 2*QSZ + ((long)(bh * 256 + kt * 8) * 4) * 64 + ln * 2;
        #pragma unroll
        for (int kc = 0; kc < 4; kc++)
            #pragma unroll
            for (int nt = 0; nt < 8; nt++) {
                uint2 kbh = *(const uint2*)(kfb + (nt * 4 + kc) * 64);
                uint2 kbl = *(const uint2*)(kfb + QSZ + (nt * 4 + kc) * 64);
                MMA16816(sc[nt], qh[kc],  kbh);
                MMA16816(sc[nt], qlo[kc], kbh);
                MMA16816(sc[nt], qh[kc],  kbl);
            }

        if (kt == qt) {
            #pragma unroll
            for (int nt = 0; nt < 8; nt++) {
                int c = kt * 64 + nt * 8 + tg * 2;
                sc[nt][0] = (c     > row0)     ? -1e30f : sc[nt][0] * 8.f;
                sc[nt][1] = (c + 1 > row0)     ? -1e30f : sc[nt][1] * 8.f;
                sc[nt][2] = (c     > row0 + 8) ? -1e30f : sc[nt][2] * 8.f;
                sc[nt][3] = (c + 1 > row0 + 8) ? -1e30f : sc[nt][3] * 8.f;
            }
        } else {
            #pragma unroll
            for (int nt = 0; nt < 8; nt++) {
                sc[nt][0] *= 8.f; sc[nt][1] *= 8.f; sc[nt][2] *= 8.f; sc[nt][3] *= 8.f;
            }
        }

        float mx0 = m0, mx1 = m1;
        #pragma unroll
        for (int nt = 0; nt < 8; nt++) {
            mx0 = fmaxf(mx0, fmaxf(sc[nt][0], sc[nt][1]));
            mx1 = fmaxf(mx1, fmaxf(sc[nt][2], sc[nt][3]));
        }
        mx0 = fmaxf(mx0, __shfl_xor_sync(0xffffffffu, mx0, 1));
        mx0 = fmaxf(mx0, __shfl_xor_sync(0xffffffffu, mx0, 2));
        mx1 = fmaxf(mx1, __shfl_xor_sync(0xffffffffu, mx1, 1));
        mx1 = fmaxf(mx1, __shfl_xor_sync(0xffffffffu, mx1, 2));
        float corr0 = fexp(m0 - mx0), corr1 = fexp(m1 - mx1);
        m0 = mx0; m1 = mx1;
        l0 *= corr0; l1 *= corr1;
        #pragma unroll
        for (int nt = 0; nt < 8; nt++) {
            sc[nt][0] = fexp(sc[nt][0] - mx0);
            sc[nt][1] = fexp(sc[nt][1] - mx0);
            sc[nt][2] = fexp(sc[nt][2] - mx1);
            sc[nt][3] = fexp(sc[nt][3] - mx1);
            l0 += sc[nt][0] + sc[nt][1];
            l1 += sc[nt][2] + sc[nt][3];
        }
        uint4 pah[4], pal[4];
        #pragma unroll
        for (int k2 = 0; k2 < 4; k2++) {
            pah[k2].x = h2u(sc[2*k2][0],   sc[2*k2][1]);
            pah[k2].y = h2u(sc[2*k2][2],   sc[2*k2][3]);
            pah[k2].z = h2u(sc[2*k2+1][0], sc[2*k2+1][1]);
            pah[k2].w = h2u(sc[2*k2+1][2], sc[2*k2+1][3]);
            pal[k2].x = h2u(flo(sc[2*k2][0]),   flo(sc[2*k2][1]));
            pal[k2].y = h2u(flo(sc[2*k2][2]),   flo(sc[2*k2][3]));
            pal[k2].z = h2u(flo(sc[2*k2+1][0]), flo(sc[2*k2+1][1]));
            pal[k2].w = h2u(flo(sc[2*k2+1][2]), flo(sc[2*k2+1][3]));
        }
        #pragma unroll
        for (int nbv = 0; nbv < 8; nbv++) {
            oc[nbv][0] *= corr0; oc[nbv][1] *= corr0;
            oc[nbv][2] *= corr1; oc[nbv][3] *= corr1;
        }
        const uint32_t* vfb = pf + 4*QSZ + ((long)(bh * 128 + kt * 4) * 8) * 64 + ln * 2;
        #pragma unroll
        for (int k2 = 0; k2 < 4; k2++)
            #pragma unroll
            for (int nbv = 0; nbv < 8; nbv++) {
                uint2 vbh = *(const uint2*)(vfb + (k2 * 8 + nbv) * 64);
                uint2 vbl = *(const uint2*)(vfb + QSZ + (k2 * 8 + nbv) * 64);
                MMA16816(oc[nbv], pah[k2], vbh);
                MMA16816(oc[nbv], pal[k2], vbh);
                MMA16816(oc[nbv], pah[k2], vbl);
            }
    }

    l0 += __shfl_xor_sync(0xffffffffu, l0, 1);
    l0 += __shfl_xor_sync(0xffffffffu, l0, 2);
    l1 += __shfl_xor_sync(0xffffffffu, l1, 1);
    l1 += __shfl_xor_sync(0xffffffffu, l1, 2);
    float inv0 = 1.f / l0, inv1 = 1.f / l1;

    int hloc = bh & 15;
    long mbG = (long)(bh >> 4) * 128 + qt * 4 + wq;
    #pragma unroll
    for (int nbv = 0; nbv < 8; nbv++) {
        int kco = hloc * 4 + (nbv >> 1);
        long base = (mbG * 64 + kco) * 128 + (g * 4 + tg) * 4 + ((nbv & 1) ? 2 : 0);
        out[base]     = h2u(oc[nbv][0] * inv0, oc[nbv][1] * inv0);
        out[base + 1] = h2u(oc[nbv][2] * inv1, oc[nbv][3] * inv1);
    }
}

// ---------------- launch ----------------------------------------------------------
extern "C" void kernel_launch(void* const* d_in, const int* in_sizes, int n_in,
                              void* d_out, int out_size) {
    const float* x   = (const float*)d_in[0];
    const float* Wq  = (const float*)d_in[1];
    const float* Wk  = (const float*)d_in[2];
    const float* Wv  = (const float*)d_in[3];
    const float* Wp  = (const float*)d_in[4];
    const float* bp  = (const float*)d_in[5];
    const float* W1  = (const float*)d_in[6];
    const float* b1  = (const float*)d_in[7];
    const float* W2  = (const float*)d_in[8];
    const float* b2  = (const float*)d_in[9];
    const float* g1  = (const float*)d_in[10];
    const float* be1 = (const float*)d_in[11];
    const float* g2  = (const float*)d_in[12];
    const float* be2 = (const float*)d_in[13];
    float* out = (float*)d_out;

    uint32_t *phA, *pff1A, *pfrag, *pwqkvB, *pwpB, *pw1B, *pw2B;
    float *px1;
    cudaGetSymbolAddress((void**)&phA,    g_hA);
    cudaGetSymbolAddress((void**)&pff1A,  g_ff1A);
    cudaGetSymbolAddress((void**)&pfrag,  g_frag);
    cudaGetSymbolAddress((void**)&px1,    g_x1);
    cudaGetSymbolAddress((void**)&pwqkvB, g_wqkvB);
    cudaGetSymbolAddress((void**)&pwpB,   g_wpB);
    cudaGetSymbolAddress((void**)&pw1B,   g_w1B);
    cudaGetSymbolAddress((void**)&pw2B,   g_w2B);

    long tq = (long)(E/16) * (E3/8) * 64;
    pack_qkv<<<(int)((tq + 255) / 256), 256>>>(Wq, Wk, Wv, pwqkvB);
    long tp = (long)(E/16) * (E/8) * 64;
    pack_w<<<(int)((tp + 255) / 256), 256>>>(Wp, E, tp, pwpB);
    long t1 = (long)(E/16) * (FE/8) * 64;
    pack_w<<<(int)((t1 + 255) / 256), 256>>>(W1, FE, t1, pw1B);
    long t2 = (long)(FE/16) * (E/8) * 64;
    pack_w<<<(int)((t2 + 255) / 256), 256>>>(W2, E, t2, pw2B);

    // LN1 -> A-perm
    ln_pack<<<BT, 256>>>(x, g1, be1, phA);
    // qkv = h @ Wqkv -> Q/K/V hi+lo fragments
    hgemm<3><<<dim3(E3/128, BT/128), 256>>>(phA, pwqkvB, nullptr, nullptr, pfrag, 64, E3, 0);
    // attention -> A-perm
    attn_mma<<<dim3(32, 64), 128>>>(pfrag, phA);
    // x1 = x + attn @ Wp + bp
    hgemm<1><<<dim3(E/128, BT/128), 256>>>(phA, pwpB, bp, x, px1, 64, E, 0);
    // LN2 -> A-perm
    ln_pack<<<BT, 256>>>(px1, g2, be2, phA);
    // ff1 = relu(h2 @ W1 + b1) -> A-perm
    hgemm<2><<<dim3(FE/128, BT/128), 256>>>(phA, pw1B, b1, nullptr, pff1A, 64, FE, 256);
    // out = x1 + ff1 @ W2 + b2
    hgemm<1><<<dim3(E/128, BT/128), 256>>>(pff1A, pw2B, b2, px1, out, 256, E, 0);
}